// round 5
// baseline (speedup 1.0000x reference)
#include <cuda_runtime.h>
#include <cuda_bf16.h>
#include <cstdint>

#define T_ 4
#define B_ 16
#define C_ 384
#define N_ 1024
#define TB_STRIDE (B_*C_*N_)   // 6291456 elements per time step

// ---------------- scratch (device globals; no allocation) ----------------
__device__ unsigned char g_xs[(size_t)T_*B_*C_*N_];          // 25 MB spike bytes
__device__ unsigned int  g_mask[(size_t)T_*B_*N_*12];        // 3 MB: 384-bit channel mask per (t,b,n)
__device__ __nv_bfloat16 g_wqT[C_*C_];                       // wqT[c][o], bf16
__device__ float         g_wpT[C_*C_];                       // wpT[c][o], fp32

// ---------------- K0: transpose weights ----------------
__global__ void k_prep(const float* __restrict__ wq, const float* __restrict__ wp) {
    int i = blockIdx.x * blockDim.x + threadIdx.x;
    if (i < C_ * C_) {
        int o = i / C_;
        int c = i - o * C_;
        g_wqT[c * C_ + o] = __float2bfloat16(wq[i]);
        g_wpT[c * C_ + o] = wp[i];
    }
}

// ---------------- K1: LIF on x (exact replication of reference math) ----------------
__global__ void k_lif_x(const float* __restrict__ x) {
    int idx = blockIdx.x * blockDim.x + threadIdx.x;
    if (idx >= TB_STRIDE) return;
    float v = 0.0f;
#pragma unroll
    for (int t = 0; t < T_; t++) {
        float xt = x[(size_t)t * TB_STRIDE + idx];
        float h = v + (xt - v) * 0.5f;       // tau = 2
        bool s = (h >= 1.0f);                // v_threshold = 1
        v = s ? 0.0f : h;                    // hard reset
        g_xs[(size_t)t * TB_STRIDE + idx] = s ? (unsigned char)1 : (unsigned char)0;
    }
}

// ---------------- K1b: pack spike bytes into 384-bit masks per (t,b,n) ----------------
// block = (tb, group of 32 n), 384 threads
__global__ void k_pack() {
    __shared__ unsigned char sb[C_][32];
    int blk = blockIdx.x;            // 0 .. T*B*32 - 1
    int ng  = blk & 31;              // N/32 = 32 groups
    int tb  = blk >> 5;              // 0 .. 63
    int n0  = ng * 32;
    int j   = threadIdx.x;           // 0 .. 383

    // load: thread j grabs 32 contiguous bytes for channel c=j
    const unsigned char* src = g_xs + ((size_t)tb * C_ + j) * N_ + n0;
    uint4 a0 = *(const uint4*)(src);
    uint4 a1 = *(const uint4*)(src + 16);
    *(uint4*)&sb[j][0]  = a0;
    *(uint4*)&sb[j][16] = a1;
    __syncthreads();

    // pack: thread j -> (n_local, word)
    int n_local = j / 12;
    int w       = j - n_local * 12;
    unsigned m = 0;
#pragma unroll
    for (int k = 0; k < 32; k++)
        m |= (sb[w * 32 + k][n_local] ? 1u : 0u) << k;
    g_mask[((size_t)tb * N_ + n0 + n_local) * 12 + w] = m;
}

// ---------------- K2: fused sparse GEMM -> bn -> LIF -> mask -> sparse GEMM -> bn ----------------
// block = (b, n); 128 threads; thread owns output rows o = tid, tid+128, tid+256; all 4 t in regs
__global__ void __launch_bounds__(128) k_main(
    const unsigned char* __restrict__ ak, const unsigned char* __restrict__ av,
    const float* __restrict__ qg, const float* __restrict__ qbeta,
    const float* __restrict__ qmean, const float* __restrict__ qvar,
    const float* __restrict__ bp,
    const float* __restrict__ pg, const float* __restrict__ pbeta,
    const float* __restrict__ pmean, const float* __restrict__ pvar,
    float* __restrict__ out)
{
    __shared__ unsigned int qmask[T_][12];
    __shared__ unsigned int smask[T_][12];

    const int n   = blockIdx.x & (N_ - 1);
    const int b   = blockIdx.x >> 10;
    const int tid = threadIdx.x;

    if (tid < T_ * 12) {
        int t = tid / 12, w = tid - t * 12;
        qmask[t][w] = g_mask[(((size_t)t * B_ + b) * N_ + n) * 12 + w];
    }

    // per-output-channel constants
    float qinv[3], qadd[3], pinv[3], padd[3], bpv[3];
#pragma unroll
    for (int r = 0; r < 3; r++) {
        int o = tid + r * 128;
        float iv = qg[o] / sqrtf(qvar[o] + 1e-5f);
        qinv[r] = iv;
        qadd[r] = qbeta[o] - qmean[o] * iv;
        float iv2 = pg[o] / sqrtf(pvar[o] + 1e-5f);
        pinv[r] = iv2;
        padd[r] = pbeta[o] - pmean[o] * iv2;
        bpv[r]  = bp[o];
    }
    __syncthreads();

    // ---- phase 1: q = wq @ xs (sparse column adds, bf16 weights, fp32 accum) ----
    float qa[T_][3];
#pragma unroll
    for (int t = 0; t < T_; t++)
#pragma unroll
        for (int r = 0; r < 3; r++) qa[t][r] = 0.0f;

#pragma unroll
    for (int t = 0; t < T_; t++) {
#pragma unroll
        for (int w = 0; w < 12; w++) {
            unsigned m = qmask[t][w];
            while (m) {
                int bit = __ffs((int)m) - 1;
                m &= m - 1;
                int c = w * 32 + bit;
                const __nv_bfloat16* row = g_wqT + c * C_;
                qa[t][0] += __bfloat162float(row[tid]);
                qa[t][1] += __bfloat162float(row[tid + 128]);
                qa[t][2] += __bfloat162float(row[tid + 256]);
            }
        }
    }

    // ---- phase 2: q_bn -> q_lif (scan over t) -> AND with (attn_k & attn_v) ----
    bool sbit[T_][3];
#pragma unroll
    for (int r = 0; r < 3; r++) {
        float v = 0.0f;
        int c = tid + r * 128;
#pragma unroll
        for (int t = 0; t < T_; t++) {
            float qn = qa[t][r] * qinv[r] + qadd[r];
            float h = v + (qn - v) * 0.5f;
            bool s = (h >= 1.0f);
            v = s ? 0.0f : h;
            bool sm = false;
            if (s) {  // only touch attn tensors when a spike actually fires
                size_t idx = (((size_t)t * B_ + b) * C_ + c) * (size_t)N_ + n;
                sm = (ak[idx] != 0) && (av[idx] != 0);
            }
            sbit[t][r] = sm;
        }
    }

    // ballot spike bits into block-wide masks (word = r*4 + warp, bit = lane)
    int warp = tid >> 5, lane = tid & 31;
#pragma unroll
    for (int t = 0; t < T_; t++) {
#pragma unroll
        for (int r = 0; r < 3; r++) {
            unsigned mk = __ballot_sync(0xffffffffu, sbit[t][r]);
            if (lane == 0) smask[t][r * 4 + warp] = mk;
        }
    }
    __syncthreads();

    // ---- phase 3: out = wp @ s (sparse, fp32 exact) + bias, then proj bn ----
    float oa[T_][3];
#pragma unroll
    for (int t = 0; t < T_; t++)
#pragma unroll
        for (int r = 0; r < 3; r++) oa[t][r] = 0.0f;

#pragma unroll
    for (int t = 0; t < T_; t++) {
#pragma unroll
        for (int w = 0; w < 12; w++) {
            unsigned m = smask[t][w];
            while (m) {
                int bit = __ffs((int)m) - 1;
                m &= m - 1;
                int c = w * 32 + bit;
                const float* row = g_wpT + c * C_;
                oa[t][0] += row[tid];
                oa[t][1] += row[tid + 128];
                oa[t][2] += row[tid + 256];
            }
        }
    }

#pragma unroll
    for (int t = 0; t < T_; t++) {
#pragma unroll
        for (int r = 0; r < 3; r++) {
            int o = tid + r * 128;
            float y = (oa[t][r] + bpv[r]) * pinv[r] + padd[r];
            out[(((size_t)t * B_ + b) * C_ + o) * (size_t)N_ + n] = y;
        }
    }
}

// ---------------- launch ----------------
extern "C" void kernel_launch(void* const* d_in, const int* in_sizes, int n_in,
                              void* d_out, int out_size) {
    const float*         x  = (const float*)d_in[0];
    const unsigned char* ak = (const unsigned char*)d_in[1];
    const unsigned char* av = (const unsigned char*)d_in[2];
    const float*         wq = (const float*)d_in[3];
    const float*         qg = (const float*)d_in[4];
    const float*         qb = (const float*)d_in[5];
    const float*         qm = (const float*)d_in[6];
    const float*         qv = (const float*)d_in[7];
    const float*         wp = (const float*)d_in[8];
    const float*         bp = (const float*)d_in[9];
    const float*         pg = (const float*)d_in[10];
    const float*         pb = (const float*)d_in[11];
    const float*         pm = (const float*)d_in[12];
    const float*         pv = (const float*)d_in[13];
    float* out = (float*)d_out;

    (void)in_sizes; (void)n_in; (void)out_size;

    k_prep<<<(C_ * C_ + 255) / 256, 256>>>(wq, wp);
    k_lif_x<<<(TB_STRIDE + 255) / 256, 256>>>(x);
    k_pack<<<T_ * B_ * (N_ / 32), 384>>>();
    k_main<<<B_ * N_, 128>>>(ak, av, qg, qb, qm, qv, bp, pg, pb, pm, pv, out);
}

// round 6
// speedup vs baseline: 1.7455x; 1.7455x over previous
#include <cuda_runtime.h>
#include <cuda_bf16.h>
#include <cstdint>

#define T_ 4
#define B_ 16
#define C_ 384
#define N_ 1024
#define TB_STRIDE (B_*C_*N_)   // elements per time step of x

// ---------------- scratch (device globals; no allocation) ----------------
__device__ unsigned int  g_mask[(size_t)T_*B_*N_*12];   // 3 MB: 384-bit channel mask per (t,b,n)
__device__ __nv_bfloat16 g_wqT[C_*C_];                  // wqT[c][o], bf16
__device__ float         g_wpT[C_*C_];                  // wpT[c][o], fp32
__device__ float         g_tmp[(size_t)T_*B_*N_*C_];    // 100 MB: out in [t,b,n,o] order

// ---------------- K0: transpose weights ----------------
__global__ void k_prep(const float* __restrict__ wq, const float* __restrict__ wp) {
    int i = blockIdx.x * blockDim.x + threadIdx.x;
    if (i < C_ * C_) {
        int o = i / C_;
        int c = i - o * C_;
        g_wqT[c * C_ + o] = __float2bfloat16(wq[i]);
        g_wpT[c * C_ + o] = wp[i];
    }
}

// ---------------- K1: fused LIF(x) + bit-pack into channel masks ----------------
// grid (N/128, C/64, B); block 128 threads (one n each); thread handles 64 channels, all t.
__global__ void __launch_bounds__(128) k_lif_pack(const float* __restrict__ x) {
    const int n  = blockIdx.x * 128 + threadIdx.x;
    const int c0 = blockIdx.y * 64;
    const int b  = blockIdx.z;

    unsigned m[T_][2];
#pragma unroll
    for (int t = 0; t < T_; t++) { m[t][0] = 0u; m[t][1] = 0u; }

#pragma unroll
    for (int w2 = 0; w2 < 2; w2++) {
#pragma unroll 8
        for (int k = 0; k < 32; k++) {
            int c = c0 + w2 * 32 + k;
            const float* px = x + ((size_t)b * C_ + c) * N_ + n;
            float v = 0.0f;
#pragma unroll
            for (int t = 0; t < T_; t++) {
                float xt = px[(size_t)t * TB_STRIDE];
                float h = v + (xt - v) * 0.5f;   // tau = 2
                bool  s = (h >= 1.0f);           // v_th = 1
                v = s ? 0.0f : h;                // hard reset
                m[t][w2] |= (s ? 1u : 0u) << k;
            }
        }
    }

#pragma unroll
    for (int t = 0; t < T_; t++)
#pragma unroll
        for (int w2 = 0; w2 < 2; w2++)
            g_mask[(((size_t)t * B_ + b) * N_ + n) * 12 + blockIdx.y * 2 + w2] = m[t][w2];
}

// ---------------- K2: fused sparse GEMM -> bn -> LIF -> mask -> sparse GEMM -> bn ----------------
// block = (b, n); 192 threads; thread owns outputs o0 = 2*tid, 2*tid+1; all 4 t in regs.
__global__ void __launch_bounds__(192) k_main(
    const unsigned char* __restrict__ ak, const unsigned char* __restrict__ av,
    const float* __restrict__ qg, const float* __restrict__ qbeta,
    const float* __restrict__ qmean, const float* __restrict__ qvar,
    const float* __restrict__ bp,
    const float* __restrict__ pg, const float* __restrict__ pbeta,
    const float* __restrict__ pmean, const float* __restrict__ pvar)
{
    __shared__ unsigned int   qmask[T_][12];
    __shared__ unsigned short list_[T_][384];
    __shared__ unsigned char  sbytes[T_][C_];
    __shared__ int            cnt_[T_];

    const int n    = blockIdx.x & (N_ - 1);
    const int b    = blockIdx.x >> 10;
    const int tid  = threadIdx.x;
    const int lane = tid & 31;
    const int warp = tid >> 5;
    const int o0   = 2 * tid;

    if (tid < T_ * 12) {
        int t = tid / 12, w = tid - t * 12;
        qmask[t][w] = g_mask[(((size_t)t * B_ + b) * N_ + n) * 12 + w];
    }
    __syncthreads();

    // compact active-channel lists: warp t handles time step t
    if (warp < T_) {
        int t = warp;
        int base = 0;
#pragma unroll
        for (int w = 0; w < 12; w++) {
            unsigned m = qmask[t][w];
            if (m & (1u << lane)) {
                int pos = base + __popc(m & ((1u << lane) - 1));
                list_[t][pos] = (unsigned short)(w * 32 + lane);
            }
            base += __popc(m);
        }
        if (lane == 0) cnt_[t] = base;
    }

    // per-output-channel constants (while compaction runs)
    float qinv0 = qg[o0]     / sqrtf(qvar[o0]     + 1e-5f);
    float qinv1 = qg[o0 + 1] / sqrtf(qvar[o0 + 1] + 1e-5f);
    float qadd0 = qbeta[o0]     - qmean[o0]     * qinv0;
    float qadd1 = qbeta[o0 + 1] - qmean[o0 + 1] * qinv1;
    float pinv0 = pg[o0]     / sqrtf(pvar[o0]     + 1e-5f);
    float pinv1 = pg[o0 + 1] / sqrtf(pvar[o0 + 1] + 1e-5f);
    float padd0 = pbeta[o0]     - pmean[o0]     * pinv0;
    float padd1 = pbeta[o0 + 1] - pmean[o0 + 1] * pinv1;
    float bp0 = bp[o0], bp1 = bp[o0 + 1];
    __syncthreads();

    // ---- phase 1: q = wq @ xs  (counted sparse column adds, bf16x2 loads) ----
    float qa0[T_], qa1[T_];
#pragma unroll
    for (int t = 0; t < T_; t++) { qa0[t] = 0.0f; qa1[t] = 0.0f; }

#pragma unroll
    for (int t = 0; t < T_; t++) {
        int K = cnt_[t];
        int i = 0;
        for (; i + 4 <= K; i += 4) {
            int c0 = list_[t][i], c1 = list_[t][i + 1];
            int c2 = list_[t][i + 2], c3 = list_[t][i + 3];
            __nv_bfloat162 v0 = *(const __nv_bfloat162*)(g_wqT + c0 * C_ + o0);
            __nv_bfloat162 v1 = *(const __nv_bfloat162*)(g_wqT + c1 * C_ + o0);
            __nv_bfloat162 v2 = *(const __nv_bfloat162*)(g_wqT + c2 * C_ + o0);
            __nv_bfloat162 v3 = *(const __nv_bfloat162*)(g_wqT + c3 * C_ + o0);
            float2 f0 = __bfloat1622float2(v0);
            float2 f1 = __bfloat1622float2(v1);
            float2 f2 = __bfloat1622float2(v2);
            float2 f3 = __bfloat1622float2(v3);
            qa0[t] += f0.x; qa1[t] += f0.y;
            qa0[t] += f1.x; qa1[t] += f1.y;
            qa0[t] += f2.x; qa1[t] += f2.y;
            qa0[t] += f3.x; qa1[t] += f3.y;
        }
        for (; i < K; i++) {
            int c = list_[t][i];
            float2 f = __bfloat1622float2(*(const __nv_bfloat162*)(g_wqT + c * C_ + o0));
            qa0[t] += f.x; qa1[t] += f.y;
        }
    }

    // ---- phase 2: q_bn -> q_lif (scan over t) -> AND with (attn_k & attn_v) ----
    {
        float v0 = 0.0f, v1 = 0.0f;
#pragma unroll
        for (int t = 0; t < T_; t++) {
            float qn0 = qa0[t] * qinv0 + qadd0;
            float qn1 = qa1[t] * qinv1 + qadd1;
            float h0 = v0 + (qn0 - v0) * 0.5f;
            float h1 = v1 + (qn1 - v1) * 0.5f;
            bool s0 = (h0 >= 1.0f);
            bool s1 = (h1 >= 1.0f);
            v0 = s0 ? 0.0f : h0;
            v1 = s1 ? 0.0f : h1;
            bool r0 = false, r1 = false;
            if (s0) {
                size_t idx = (((size_t)t * B_ + b) * C_ + o0) * (size_t)N_ + n;
                r0 = (ak[idx] != 0) && (av[idx] != 0);
            }
            if (s1) {
                size_t idx = (((size_t)t * B_ + b) * C_ + o0 + 1) * (size_t)N_ + n;
                r1 = (ak[idx] != 0) && (av[idx] != 0);
            }
            sbytes[t][o0]     = r0 ? 1 : 0;
            sbytes[t][o0 + 1] = r1 ? 1 : 0;
        }
    }
    __syncthreads();

    // compact post-attention spike lists (reuse list_/cnt_)
    if (warp < T_) {
        int t = warp;
        int base = 0;
#pragma unroll
        for (int w = 0; w < 12; w++) {
            bool a = sbytes[t][w * 32 + lane] != 0;
            unsigned m = __ballot_sync(0xffffffffu, a);
            if (a) {
                int pos = base + __popc(m & ((1u << lane) - 1));
                list_[t][pos] = (unsigned short)(w * 32 + lane);
            }
            base += __popc(m);
        }
        if (lane == 0) cnt_[t] = base;
    }
    __syncthreads();

    // ---- phase 3: out = wp @ s (sparse, fp32 exact) ----
    float oa0[T_], oa1[T_];
#pragma unroll
    for (int t = 0; t < T_; t++) { oa0[t] = 0.0f; oa1[t] = 0.0f; }

#pragma unroll
    for (int t = 0; t < T_; t++) {
        int K = cnt_[t];
        for (int i = 0; i < K; i++) {
            int c = list_[t][i];
            float2 w = *(const float2*)(g_wpT + c * C_ + o0);
            oa0[t] += w.x; oa1[t] += w.y;
        }
    }

    // ---- epilogue: +bias, proj bn, store n-major (coalesced) ----
#pragma unroll
    for (int t = 0; t < T_; t++) {
        float2 y;
        y.x = (oa0[t] + bp0) * pinv0 + padd0;
        y.y = (oa1[t] + bp1) * pinv1 + padd1;
        *(float2*)(g_tmp + (((size_t)t * B_ + b) * N_ + n) * C_ + o0) = y;
    }
}

// ---------------- K3: transpose [t,b,n,o] -> [t,b,o,n] ----------------
__global__ void __launch_bounds__(256) k_tr(float* __restrict__ out) {
    __shared__ float tile[32][33];
    const int tb = blockIdx.z;
    const int o_base = blockIdx.y * 32;
    const int n_base = blockIdx.x * 32;
    const int tx = threadIdx.x;
    const int ty = threadIdx.y;   // 32 x 8

    const float* src = g_tmp + ((size_t)tb * N_ + n_base) * C_ + o_base;
#pragma unroll
    for (int i = 0; i < 32; i += 8)
        tile[ty + i][tx] = src[(size_t)(ty + i) * C_ + tx];   // tile[n_local][o_local]
    __syncthreads();

    float* dst = out + ((size_t)tb * C_ + o_base) * N_ + n_base;
#pragma unroll
    for (int i = 0; i < 32; i += 8)
        dst[(size_t)(ty + i) * N_ + tx] = tile[tx][ty + i];
}

// ---------------- launch ----------------
extern "C" void kernel_launch(void* const* d_in, const int* in_sizes, int n_in,
                              void* d_out, int out_size) {
    const float*         x  = (const float*)d_in[0];
    const unsigned char* ak = (const unsigned char*)d_in[1];
    const unsigned char* av = (const unsigned char*)d_in[2];
    const float*         wq = (const float*)d_in[3];
    const float*         qg = (const float*)d_in[4];
    const float*         qb = (const float*)d_in[5];
    const float*         qm = (const float*)d_in[6];
    const float*         qv = (const float*)d_in[7];
    const float*         wp = (const float*)d_in[8];
    const float*         bp = (const float*)d_in[9];
    const float*         pg = (const float*)d_in[10];
    const float*         pb = (const float*)d_in[11];
    const float*         pm = (const float*)d_in[12];
    const float*         pv = (const float*)d_in[13];
    float* out = (float*)d_out;

    (void)in_sizes; (void)n_in; (void)out_size;

    k_prep<<<(C_ * C_ + 255) / 256, 256>>>(wq, wp);
    k_lif_pack<<<dim3(N_ / 128, C_ / 64, B_), 128>>>(x);
    k_main<<<B_ * N_, 192>>>(ak, av, qg, qb, qm, qv, bp, pg, pb, pm, pv);
    k_tr<<<dim3(N_ / 32, C_ / 32, T_ * B_), dim3(32, 8)>>>(out);
}